// round 4
// baseline (speedup 1.0000x reference)
#include <cuda_runtime.h>
#include <math.h>

#define NN 65536
#define EE 1048576
#define BB 256

// ---------------- device scratch (static globals; no allocation) ----------------
__device__ __align__(16) float g_h[NN * 64];      // node state h / out
__device__ __align__(16) float g_tmp[NN * 64];    // conv output
__device__ __align__(16) float g_m[NN * 64];      // scatter accumulator
__device__ __align__(16) float g_gix[NN * 192];   // precomputed W_ih[:,64:96]@x + b_ih
__device__ __align__(16) float g_Wall[64 * 384];  // [k][o] o<192: W_ih[o][k]; o>=192: W_hh[o-192][k]
__device__ __align__(16) float g_Wx[32 * 256];    // [k][o] o<64: W_mlp[o][k]; o>=64: W_ih[o-64][64+k]
__device__ float g_bx[256];
__device__ __align__(16) float g_Wc[64 * 64];     // [k][o] = W_conv[o][k]
__device__ float g_e[NN];
__device__ __align__(16) float g_q[BB * 64];      // set2set hidden (= q)
__device__ __align__(16) float g_c[BB * 64];
__device__ __align__(16) float g_qstar[BB * 128];
__device__ unsigned g_emax[BB];
__device__ float g_asum[BB];
__device__ __align__(16) float g_r[BB * 64];
__device__ int g_is64e, g_is64b;

__device__ __forceinline__ float sigm(float x) { return 1.0f / (1.0f + expf(-x)); }

// ---------------- dtype detection (int32 vs int64 index buffers) ----------------
// int64 little-endian with values < 2^31 has every odd 32-bit word == 0.
// Sample the TAIL of each buffer (batch is sorted so its head is all zeros either way).
__global__ void k_detect(const int* ei, const int* bt) {
    if (threadIdx.x == 0 && blockIdx.x == 0) {
        int z = 0;
        for (int k = 0; k < 32; k++) z |= ei[2 * EE - 1 - 2 * k];   // odd words near tail (valid for both dtypes)
        g_is64e = (z == 0) ? 1 : 0;
        int zb = 0;
        for (int k = 0; k < 32; k++) zb |= bt[NN - 1 - 2 * k];      // odd words near tail
        g_is64b = (zb == 0) ? 1 : 0;
    }
}

__device__ __forceinline__ int ld_idx(const int* p, int i, int is64) {
    return is64 ? p[2 * i] : p[i];
}

// ---------------- weight re-layout ----------------
__global__ void k_prep(const float* W_mlp, const float* b_mlp,
                       const float* W_ih, const float* b_ih,
                       const float* W_hh, const float* W_conv) {
    int t = blockIdx.x * blockDim.x + threadIdx.x;
    if (t < 64 * 384) {
        int k = t / 384, o = t % 384;
        g_Wall[t] = (o < 192) ? W_ih[o * 96 + k] : W_hh[(o - 192) * 64 + k];
    }
    if (t < 32 * 256) {
        int k = t / 256, o = t % 256;
        g_Wx[t] = (o < 64) ? W_mlp[o * 32 + k] : W_ih[(o - 64) * 96 + 64 + k];
    }
    if (t < 256) g_bx[t] = (t < 64) ? b_mlp[t] : b_ih[t - 64];
    if (t < 64 * 64) {
        int k = t / 64, o = t % 64;
        g_Wc[t] = W_conv[o * 64 + k];
    }
}

// ---------------- zeroing kernels ----------------
__global__ void k_zero_m() {
    int i = blockIdx.x * 256 + threadIdx.x;           // grid: NN*64/4/256 = 4096
    ((float4*)g_m)[i] = make_float4(0.f, 0.f, 0.f, 0.f);
}
__global__ void k_zero_s2s() {
    int i = blockIdx.x * 256 + threadIdx.x;           // grid: 32 -> 8192 threads
    float4 z = make_float4(0.f, 0.f, 0.f, 0.f);
    if (i < BB * 128 / 4) ((float4*)g_qstar)[i] = z;
    if (i < BB * 64 / 4) { ((float4*)g_q)[i] = z; ((float4*)g_c)[i] = z; }
}

// ---------------- fused node MLP + gix precompute: [N,32] @ [32,256] ----------------
// 32 nodes/block, 256 threads; thread tile = 4 nodes x 8 outputs.
__global__ __launch_bounds__(256) void k_mlp(const float* x) {
    __shared__ float xs[32][33];
    __shared__ float Ws[32][256];
    int tid = threadIdx.x;
    int nb = blockIdx.x * 32;
    for (int i = tid; i < 32 * 32; i += 256) xs[i >> 5][i & 31] = x[nb * 32 + i];
    for (int i = tid; i < 32 * 256 / 4; i += 256) ((float4*)Ws)[i] = ((const float4*)g_Wx)[i];
    __syncthreads();
    int tg = tid & 31;   // outputs [tg*8, tg*8+8)
    int tn = tid >> 5;   // nodes   [tn*4, tn*4+4)
    float acc[4][8];
#pragma unroll
    for (int n = 0; n < 4; n++)
#pragma unroll
        for (int j = 0; j < 8; j++) acc[n][j] = 0.f;
#pragma unroll
    for (int k = 0; k < 32; k++) {
        float4 w0 = *(float4*)&Ws[k][tg * 8];
        float4 w1 = *(float4*)&Ws[k][tg * 8 + 4];
#pragma unroll
        for (int n = 0; n < 4; n++) {
            float in = xs[tn * 4 + n][k];
            acc[n][0] += in * w0.x; acc[n][1] += in * w0.y;
            acc[n][2] += in * w0.z; acc[n][3] += in * w0.w;
            acc[n][4] += in * w1.x; acc[n][5] += in * w1.y;
            acc[n][6] += in * w1.z; acc[n][7] += in * w1.w;
        }
    }
#pragma unroll
    for (int n = 0; n < 4; n++) {
        int node = nb + tn * 4 + n;
#pragma unroll
        for (int j = 0; j < 8; j++) {
            int o = tg * 8 + j;
            float v = acc[n][j] + g_bx[o];
            if (o < 64) g_h[node * 64 + o] = v;
            else        g_gix[node * 192 + (o - 64)] = v;
        }
    }
}

// ---------------- conv: tmp = h @ Wc + b_conv, [N,64]@[64,64] ----------------
// 64 nodes/block, 256 threads; thread tile 4 nodes x 4 outputs.
__global__ __launch_bounds__(256) void k_conv(const float* b_conv) {
    __shared__ float hs[64][65];
    __shared__ float Ws[64][64];
    int tid = threadIdx.x;
    int nb = blockIdx.x * 64;
    for (int i = tid; i < 64 * 64; i += 256) {
        hs[i >> 6][i & 63] = g_h[nb * 64 + i];
        Ws[i >> 6][i & 63] = g_Wc[i];
    }
    __syncthreads();
    int tg = tid & 15;   // outputs [tg*4,+4)
    int tn = tid >> 4;   // nodes [tn*4,+4)
    float acc[4][4];
#pragma unroll
    for (int n = 0; n < 4; n++)
#pragma unroll
        for (int j = 0; j < 4; j++) acc[n][j] = 0.f;
#pragma unroll 8
    for (int k = 0; k < 64; k++) {
        float4 w = *(float4*)&Ws[k][tg * 4];
#pragma unroll
        for (int n = 0; n < 4; n++) {
            float in = hs[tn * 4 + n][k];
            acc[n][0] += in * w.x; acc[n][1] += in * w.y;
            acc[n][2] += in * w.z; acc[n][3] += in * w.w;
        }
    }
    float b0 = b_conv[tg * 4], b1 = b_conv[tg * 4 + 1], b2 = b_conv[tg * 4 + 2], b3 = b_conv[tg * 4 + 3];
#pragma unroll
    for (int n = 0; n < 4; n++) {
        int node = nb + tn * 4 + n;
        *(float4*)&g_tmp[node * 64 + tg * 4] =
            make_float4(acc[n][0] + b0, acc[n][1] + b1, acc[n][2] + b2, acc[n][3] + b3);
    }
}

// ---------------- edge scatter: m[dst] += tmp[src], 16 lanes per edge ----------------
__global__ __launch_bounds__(256) void k_scatter(const int* ei) {
    int is64 = g_is64e;
    int t = blockIdx.x * 256 + threadIdx.x;   // 16M threads
    int e = t >> 4, c = t & 15;
    int src = ld_idx(ei, e, is64);
    int dst = ld_idx(ei, EE + e, is64);
    float4 v = ((const float4*)g_tmp)[src * 16 + c];
    float* p = g_m + ((size_t)dst * 64 + c * 4);
    asm volatile("red.global.add.v4.f32 [%0], {%1,%2,%3,%4};" ::
                 "l"(p), "f"(v.x), "f"(v.y), "f"(v.z), "f"(v.w) : "memory");
}

// ---------------- GRU step: gi = Wih_m@m + gix ; gh = Whh@h + b_hh ; combine ----------------
// 32 nodes/block, 256 threads; GEMM [32,64]@[64,384]; thread tile 4 nodes x 12 outputs.
__global__ __launch_bounds__(256) void k_gru(const float* b_hh) {
    extern __shared__ float sm[];
    float* Wall = sm;                  // 64*384
    float* ms   = Wall + 64 * 384;     // 32*65
    float* hsm  = ms + 32 * 65;        // 32*65
    float* S    = hsm + 32 * 65;       // 32*384
    int tid = threadIdx.x;
    int nb = blockIdx.x * 32;
    for (int i = tid; i < 64 * 384 / 4; i += 256) ((float4*)Wall)[i] = ((const float4*)g_Wall)[i];
    for (int i = tid; i < 32 * 64; i += 256) {
        int n = i >> 6, k = i & 63;
        ms[n * 65 + k]  = g_m[nb * 64 + i];
        hsm[n * 65 + k] = g_h[nb * 64 + i];
    }
    __syncthreads();
    int to = tid & 31;      // output group: [to*12, +12) of 384
    int tn = tid >> 5;      // nodes [tn*4,+4)
    int obase = to * 12;
    const float* inrow = (obase < 192) ? ms : hsm;
    float acc[4][12];
#pragma unroll
    for (int n = 0; n < 4; n++)
#pragma unroll
        for (int j = 0; j < 12; j++) acc[n][j] = 0.f;
#pragma unroll 4
    for (int k = 0; k < 64; k++) {
        float4 w0 = *(float4*)&Wall[k * 384 + obase];
        float4 w1 = *(float4*)&Wall[k * 384 + obase + 4];
        float4 w2 = *(float4*)&Wall[k * 384 + obase + 8];
#pragma unroll
        for (int n = 0; n < 4; n++) {
            float in = inrow[(tn * 4 + n) * 65 + k];
            acc[n][0] += in * w0.x; acc[n][1] += in * w0.y; acc[n][2]  += in * w0.z; acc[n][3]  += in * w0.w;
            acc[n][4] += in * w1.x; acc[n][5] += in * w1.y; acc[n][6]  += in * w1.z; acc[n][7]  += in * w1.w;
            acc[n][8] += in * w2.x; acc[n][9] += in * w2.y; acc[n][10] += in * w2.z; acc[n][11] += in * w2.w;
        }
    }
#pragma unroll
    for (int n = 0; n < 4; n++)
#pragma unroll
        for (int j = 0; j < 12; j++) S[(tn * 4 + n) * 384 + obase + j] = acc[n][j];
    __syncthreads();
    for (int it = tid; it < 32 * 64; it += 256) {
        int n = it >> 6, j = it & 63;
        int node = nb + n;
        const float* gx = g_gix + (size_t)node * 192;
        float gir = S[n * 384 + j]        + gx[j];
        float giz = S[n * 384 + 64 + j]   + gx[64 + j];
        float gin = S[n * 384 + 128 + j]  + gx[128 + j];
        float ghr = S[n * 384 + 192 + j]  + b_hh[j];
        float ghz = S[n * 384 + 256 + j]  + b_hh[64 + j];
        float ghn = S[n * 384 + 320 + j]  + b_hh[128 + j];
        float r = sigm(gir + ghr);
        float z = sigm(giz + ghz);
        float ng = tanhf(gin + r * ghn);
        float hold = hsm[n * 65 + j];
        g_h[node * 64 + j] = (1.f - z) * ng + z * hold;
    }
}

// ---------------- Set2Set LSTM cell (one block per graph) + accumulator reset ----------------
__global__ __launch_bounds__(256) void k_lstm(const float* Wih, const float* Whh,
                                              const float* bih, const float* bhh) {
    __shared__ float qs[128], hs_[64], gsm[256];
    int g = blockIdx.x, tid = threadIdx.x;
    if (tid < 128) qs[tid] = g_qstar[g * 128 + tid];
    if (tid < 64) hs_[tid] = g_q[g * 64 + tid];
    __syncthreads();
    float acc = bih[tid] + bhh[tid];
    const float* wr = Wih + tid * 128;
#pragma unroll 8
    for (int k = 0; k < 128; k++) acc += wr[k] * qs[k];
    const float* wh = Whh + tid * 64;
#pragma unroll 8
    for (int k = 0; k < 64; k++) acc += wh[k] * hs_[k];
    gsm[tid] = acc;
    __syncthreads();
    if (tid < 64) {
        float i = sigm(gsm[tid]);
        float f = sigm(gsm[64 + tid]);
        float gg = tanhf(gsm[128 + tid]);
        float o = sigm(gsm[192 + tid]);
        float c = f * g_c[g * 64 + tid] + i * gg;
        float h = o * tanhf(c);
        g_c[g * 64 + tid] = c;
        g_q[g * 64 + tid] = h;
        g_r[g * 64 + tid] = 0.f;      // reset attention accumulators for this step
    }
    if (tid == 64) { g_asum[g] = 0.f; g_emax[g] = 0u; }
}

// ---------------- attention pass 1: e[n] = <h[n], q[batch[n]]>, segment max ----------------
__global__ __launch_bounds__(256) void k_att_e(const int* bt) {
    int n = blockIdx.x * 256 + threadIdx.x;
    int g = ld_idx(bt, n, g_is64b);
    const float4* hv = ((const float4*)g_h) + (size_t)n * 16;
    const float4* qv = ((const float4*)g_q) + (size_t)g * 16;
    float e = 0.f;
#pragma unroll
    for (int c = 0; c < 16; c++) {
        float4 a = hv[c], b = qv[c];
        e += a.x * b.x + a.y * b.y + a.z * b.z + a.w * b.w;
    }
    g_e[n] = e;
    unsigned u = __float_as_uint(e);
    u = (u >> 31) ? ~u : (u | 0x80000000u);
    atomicMax(&g_emax[g], u);
}

// ---------------- attention pass 2: a=exp(e-emax), asum, r += a*h (sorted-batch flush) ----------------
__global__ __launch_bounds__(256) void k_att_r(const int* bt) {
    __shared__ float as_[64];
    __shared__ int gs[64];
    int tid = threadIdx.x;
    int base = blockIdx.x * 64;
    if (tid < 64) {
        int n = base + tid;
        int g = ld_idx(bt, n, g_is64b);
        unsigned u = g_emax[g];
        float emax = (u == 0u) ? 0.f : ((u >> 31) ? __uint_as_float(u & 0x7fffffffu)
                                                  : __uint_as_float(~u));
        float a = expf(g_e[n] - emax);
        as_[tid] = a; gs[tid] = g;
        atomicAdd(&g_asum[g], a);
    }
    __syncthreads();
    int j = tid & 63, grp = tid >> 6;          // 4 groups x 16 nodes
    float sum = 0.f;
    int pg = gs[grp * 16];
#pragma unroll
    for (int i = 0; i < 16; i++) {
        int idx = grp * 16 + i;
        int g = gs[idx];
        if (g != pg) { atomicAdd(&g_r[pg * 64 + j], sum); sum = 0.f; pg = g; }
        sum += as_[idx] * g_h[(size_t)(base + idx) * 64 + j];
    }
    atomicAdd(&g_r[pg * 64 + j], sum);
}

// ---------------- attention finalize + build q_star ----------------
__global__ void k_fin() {
    int t = blockIdx.x * 256 + threadIdx.x;   // grid 64 -> 16384
    int g = t >> 6, j = t & 63;
    float asum = fmaxf(g_asum[g], 1e-16f);
    g_qstar[g * 128 + 64 + j] = g_r[g * 64 + j] / asum;
    g_qstar[g * 128 + j] = g_q[g * 64 + j];
}

// ---------------- head: relu(qstar@W1^T+b1) @ W2^T + b2 -> log_softmax ----------------
__global__ __launch_bounds__(64) void k_head(const float* W1, const float* b1,
                                             const float* W2, const float* b2, float* out) {
    __shared__ float qs[128], hsm[64], lg[4];
    int g = blockIdx.x, tid = threadIdx.x;
    qs[tid] = g_qstar[g * 128 + tid];
    qs[64 + tid] = g_qstar[g * 128 + 64 + tid];
    __syncthreads();
    float acc = b1[tid];
    const float* w = W1 + tid * 128;
#pragma unroll 8
    for (int k = 0; k < 128; k++) acc += w[k] * qs[k];
    hsm[tid] = fmaxf(acc, 0.f);
    __syncthreads();
    if (tid < 4) {
        float a = b2[tid];
        const float* w2 = W2 + tid * 64;
#pragma unroll 8
        for (int k = 0; k < 64; k++) a += w2[k] * hsm[k];
        lg[tid] = a;
    }
    __syncthreads();
    if (tid < 4) {
        float m = fmaxf(fmaxf(lg[0], lg[1]), fmaxf(lg[2], lg[3]));
        float s = expf(lg[0] - m) + expf(lg[1] - m) + expf(lg[2] - m) + expf(lg[3] - m);
        out[g * 4 + tid] = lg[tid] - m - logf(s);
    }
}

// ---------------- launch ----------------
extern "C" void kernel_launch(void* const* d_in, const int* in_sizes, int n_in,
                              void* d_out, int out_size) {
    const float* x       = (const float*)d_in[0];
    const int*   ei      = (const int*)d_in[1];
    const int*   bt      = (const int*)d_in[2];
    const float* W_mlp   = (const float*)d_in[3];
    const float* b_mlp   = (const float*)d_in[4];
    const float* W_conv  = (const float*)d_in[5];
    const float* b_conv  = (const float*)d_in[6];
    const float* gWih    = (const float*)d_in[7];
    const float* gWhh    = (const float*)d_in[8];
    const float* gbih    = (const float*)d_in[9];
    const float* gbhh    = (const float*)d_in[10];
    const float* lWih    = (const float*)d_in[11];
    const float* lWhh    = (const float*)d_in[12];
    const float* lbih    = (const float*)d_in[13];
    const float* lbhh    = (const float*)d_in[14];
    const float* W1      = (const float*)d_in[15];
    const float* b1      = (const float*)d_in[16];
    const float* W2      = (const float*)d_in[17];
    const float* b2      = (const float*)d_in[18];
    float* out = (float*)d_out;

    static bool attr_set = false;
    const int GRU_SMEM = (64 * 384 + 2 * 32 * 65 + 32 * 384) * 4;  // 164096 B
    if (!attr_set) {
        cudaFuncSetAttribute(k_gru, cudaFuncAttributeMaxDynamicSharedMemorySize, GRU_SMEM);
        attr_set = true;
    }

    k_detect<<<1, 32>>>(ei, bt);
    k_prep<<<96, 256>>>(W_mlp, b_mlp, gWih, gbih, gWhh, W_conv);
    k_mlp<<<NN / 32, 256>>>(x);

    for (int s = 0; s < 2; s++) {
        k_conv<<<NN / 64, 256>>>(b_conv);
        k_zero_m<<<NN * 64 / 4 / 256, 256>>>();
        k_scatter<<<(EE * 16) / 256, 256>>>(ei);
        k_gru<<<NN / 32, 256, GRU_SMEM>>>(gbhh);
    }

    k_zero_s2s<<<32, 256>>>();
    for (int t = 0; t < 3; t++) {
        k_lstm<<<BB, 256>>>(lWih, lWhh, lbih, lbhh);
        k_att_e<<<NN / 256, 256>>>(bt);
        k_att_r<<<NN / 64, 256>>>(bt);
        k_fin<<<BB * 64 / 256, 256>>>();
    }
    k_head<<<BB, 64>>>(W1, b1, W2, b2, out);
}